// round 6
// baseline (speedup 1.0000x reference)
#include <cuda_runtime.h>
#include <cstdint>

typedef unsigned long long ULL;

// ---------- packed fp32x2 helpers ----------
__device__ __forceinline__ void ffma2(ULL &d, ULL a, ULL b) {
    asm("fma.rn.f32x2 %0, %1, %2, %0;" : "+l"(d) : "l"(a), "l"(b));
}
__device__ __forceinline__ float2 unpack2(ULL v) {
    float2 f; asm("mov.b64 {%0,%1}, %2;" : "=f"(f.x), "=f"(f.y) : "l"(v)); return f;
}
__device__ __forceinline__ ULL pack2(float lo, float hi) {
    ULL r; asm("mov.b64 %0, {%1,%2};" : "=l"(r) : "f"(lo), "f"(hi)); return r;
}
__device__ __forceinline__ ULL dup2(float a) {
    ULL r; asm("mov.b64 %0, {%1,%1};" : "=l"(r) : "f"(a)); return r;
}

// ---------- activations: single-MUFU tanh ----------
__device__ __forceinline__ float tanh_ap(float x) {
    float r; asm("tanh.approx.f32 %0, %1;" : "=f"(r) : "f"(x)); return r;
}
__device__ __forceinline__ float sig_ap(float x) {
    return fmaf(0.5f, tanh_ap(0.5f * x), 0.5f);
}

// ---------- cp.async 16B ----------
__device__ __forceinline__ void cp16(uint32_t dst_smem, const void* src) {
    asm volatile("cp.async.cg.shared.global [%0], [%1], 16;" :: "r"(dst_smem), "l"(src) : "memory");
}

// ---------- constants ----------
constexpr int B = 512, T = 512;
constexpr long BT = (long)B * T;
constexpr int RC = 8;              // batch rows per LSTM CTA (1 CTA/SM)
constexpr int HW = 16;             // l0 history window (timesteps)

// ---------- scratch ----------
__device__ __align__(16) float g_h0T[128 * BT];   // layer-0 out, feature-major [k][b*T+t]
__device__ __align__(16) float g_xp1[BT * 512];   // layer-1 preacts [b*T+t][n]
__device__ __align__(16) ULL   g_Btd[128 * 512];  // Wih_l1^T, values duplicated (b,b)
__device__ float g_pooled[B * 128];

// =======================================================================
// Layer-0 biLSTM. grid (64, 2), block 256, 1 CTA/SM.
// Thread owns gate row g*64+u (32 ULL weight regs), computes it for 8 batch
// rows; merged dot+combine per j; 1 barrier per step for 8 rows.
// h0 written TRANSPOSED via 16-step smem history (coalesced flush).
// =======================================================================
__global__ __launch_bounds__(256, 1) void lstm_l0(
    const float* __restrict__ x,
    const float* __restrict__ Wih_f, const float* __restrict__ Whh_f, const float* __restrict__ b_f,
    const float* __restrict__ Wih_b, const float* __restrict__ Whh_b, const float* __restrict__ b_b)
{
    const int dir = blockIdx.y;
    const int b0  = blockIdx.x * RC;
    const int tid = threadIdx.x;
    const int u   = tid >> 2;
    const int g   = tid & 3;
    const int row = g * 64 + u;

    const float* Wih = dir ? Wih_b : Wih_f;
    const float* Whh = dir ? Whh_b : Whh_f;
    const float* bb  = dir ? b_b   : b_f;

    __shared__ __align__(16) float h_s[2][RC * 64];
    __shared__ __align__(16) float4 x_s[2][RC];
    __shared__ __align__(16) float hist[RC][64][HW + 4];   // 40KB, pad kills conflicts

    ULL w2[32];
    {
        const ULL* wp = (const ULL*)(Whh + row * 64);
        #pragma unroll
        for (int i = 0; i < 32; i++) w2[i] = wp[i];
    }
    const float4 wih = *(const float4*)(Wih + row * 4);
    const float bias = bb[row];

    const int lane = tid & 31;
    const int qb   = lane & ~3;

    for (int i = tid; i < RC * 64; i += 256) h_s[0][i] = 0.f;
    if (tid < RC) {
        const int t0 = dir ? (T - 1) : 0;
        x_s[0][tid] = *(const float4*)(x + ((long)(b0 + tid) * T + t0) * 4);
    }
    __syncthreads();

    float c[RC];
    #pragma unroll
    for (int j = 0; j < RC; j++) c[j] = 0.f;
    int p = 0;

    for (int s = 0; s < T; s++) {
        const int t = dir ? (T - 1 - s) : s;
        if (tid < RC) {
            const int sn = (s + 1 < T) ? s + 1 : s;
            const int tn = dir ? (T - 1 - sn) : sn;
            x_s[p ^ 1][tid] = *(const float4*)(x + ((long)(b0 + tid) * T + tn) * 4);
        }

        #pragma unroll
        for (int j = 0; j < RC; j++) {
            ULL a0 = 0, a1 = 0;
            const ulonglong2* h4 = (const ulonglong2*)(h_s[p] + j * 64);
            #pragma unroll
            for (int k = 0; k < 16; k++) {
                ulonglong2 hv = h4[k];
                ffma2(a0, w2[2 * k],     hv.x);
                ffma2(a1, w2[2 * k + 1], hv.y);
            }
            const float2 f0 = unpack2(a0), f1 = unpack2(a1);
            const float4 xv = x_s[p][j];
            float pre = f0.x + f0.y + f1.x + f1.y + bias
                      + wih.x * xv.x + wih.y * xv.y + wih.z * xv.z + wih.w * xv.w;

            const float act = (g == 2) ? tanh_ap(pre) : sig_ap(pre);
            const float iv = __shfl_sync(0xffffffffu, act, qb + 0);
            const float fv = __shfl_sync(0xffffffffu, act, qb + 1);
            const float gv = __shfl_sync(0xffffffffu, act, qb + 2);
            const float ov = __shfl_sync(0xffffffffu, act, qb + 3);
            c[j] = fmaf(fv, c[j], iv * gv);
            const float h = ov * tanh_ap(c[j]);
            if (g == 0) {
                h_s[p ^ 1][j * 64 + u] = h;
                hist[j][u][t & (HW - 1)] = h;
            }
        }
        p ^= 1;
        __syncthreads();

        if ((s & (HW - 1)) == HW - 1) {
            const int tbase = t & ~(HW - 1);
            // flush: RC*64 units x 4 float4 = 2048 stores / 256 thr = 8 each
            #pragma unroll
            for (int w = 0; w < 8; w++) {
                const int e   = tid + w * 256;
                const int tw4 = e & 3;
                const int ju  = e >> 2;
                const int j   = ju >> 6, uu = ju & 63;
                const float4 v = *(const float4*)(&hist[j][uu][tw4 * 4]);
                *(float4*)(g_h0T + (long)(dir * 64 + uu) * BT + (long)(b0 + j) * T + tbase + tw4 * 4) = v;
            }
            __syncthreads();
        }
    }
}

// =======================================================================
// Prep: g_Btd[k][n] = dup2(Wih_l1[n][k])  (n = dir*256 + gate_row)
// =======================================================================
__global__ void prep_btd(const float* __restrict__ Wf, const float* __restrict__ Wb)
{
    const int idx = blockIdx.x * 512 + threadIdx.x;   // 65536
    const int k = idx >> 9, n = idx & 511;
    const float* W = (n & 256) ? Wb : Wf;
    g_Btd[idx] = dup2(W[(n & 255) * 128 + k]);
}

// =======================================================================
// xp1 GEMM (R5 mainloop/epilogue, slab loads via cp.async).
// 128m x 128n tile, K split 2x64, 97KB smem, 2 CTAs/SM. grid (2048,4), blk 256.
// =======================================================================
constexpr int AP = 132;
constexpr int SMEM_GEMM = 64 * AP * 4 + 64 * 128 * 8;   // 99328 B

__global__ __launch_bounds__(256, 2) void gemm_xp1(
    const float* __restrict__ bias_f, const float* __restrict__ bias_b)
{
    extern __shared__ char smraw[];
    float* As  = (float*)smraw;                  // [64][AP]   k-major, m fastest
    ULL*   Bsd = (ULL*)(smraw + 64 * AP * 4);    // [64][128]  dup'd pairs
    const uint32_t asB = (uint32_t)__cvta_generic_to_shared(As);
    const uint32_t bsB = (uint32_t)__cvta_generic_to_shared(Bsd);
    const int tid = threadIdx.x;
    const long m0 = (long)blockIdx.x * 128;
    const int  n0 = blockIdx.y * 128;

    const int tx = tid & 15;        // n-pair selector
    const int ty = tid >> 4;        // m-octet

    ULL acc[4][8];
    #pragma unroll
    for (int i = 0; i < 4; i++)
        #pragma unroll
        for (int j = 0; j < 8; j++) acc[i][j] = 0;

    for (int kc = 0; kc < 2; kc++) {
        const int k0 = kc * 64;
        __syncthreads();
        // A slab: 64 x 128 floats, straight copy (already k-major)
        #pragma unroll
        for (int i = 0; i < 8; i++) {
            const int e = tid + i * 256;
            const int k = e >> 5, m4 = (e & 31) * 4;
            cp16(asB + (uint32_t)(k * AP + m4) * 4, g_h0T + (long)(k0 + k) * BT + m0 + m4);
        }
        // B slab: 64 x 128 ULL
        #pragma unroll
        for (int i = 0; i < 8; i++) {
            const int e = tid + i * 256;
            const int k = e >> 5, w = e & 31;
            cp16(bsB + (uint32_t)(k * 128 + w * 2) * 8, g_Btd + (long)(k0 + k) * 512 + n0 + w * 2);
        }
        #pragma unroll
        for (int i = 0; i < 8; i++) {
            const int e = tid + i * 256;
            const int k = e >> 5, w = e & 31;
            cp16(bsB + (uint32_t)(k * 128 + 64 + w * 2) * 8, g_Btd + (long)(k0 + k) * 512 + n0 + 64 + w * 2);
        }
        asm volatile("cp.async.commit_group;");
        asm volatile("cp.async.wait_group 0;" ::: "memory");
        __syncthreads();

        #pragma unroll 4
        for (int k = 0; k < 64; k++) {
            const ulonglong2* ap = (const ulonglong2*)(As + k * AP + ty * 8);
            const ulonglong2 aA = ap[0], aB = ap[1];            // 4 m-pairs
            const ULL* brow = Bsd + k * 128 + tx * 2;
            const ulonglong2 b0p = *(const ulonglong2*)(brow);        // n = tx*2, +1
            const ulonglong2 b1p = *(const ulonglong2*)(brow + 32);
            const ulonglong2 b2p = *(const ulonglong2*)(brow + 64);
            const ulonglong2 b3p = *(const ulonglong2*)(brow + 96);
            ffma2(acc[0][0], aA.x, b0p.x); ffma2(acc[1][0], aA.y, b0p.x);
            ffma2(acc[2][0], aB.x, b0p.x); ffma2(acc[3][0], aB.y, b0p.x);
            ffma2(acc[0][1], aA.x, b0p.y); ffma2(acc[1][1], aA.y, b0p.y);
            ffma2(acc[2][1], aB.x, b0p.y); ffma2(acc[3][1], aB.y, b0p.y);
            ffma2(acc[0][2], aA.x, b1p.x); ffma2(acc[1][2], aA.y, b1p.x);
            ffma2(acc[2][2], aB.x, b1p.x); ffma2(acc[3][2], aB.y, b1p.x);
            ffma2(acc[0][3], aA.x, b1p.y); ffma2(acc[1][3], aA.y, b1p.y);
            ffma2(acc[2][3], aB.x, b1p.y); ffma2(acc[3][3], aB.y, b1p.y);
            ffma2(acc[0][4], aA.x, b2p.x); ffma2(acc[1][4], aA.y, b2p.x);
            ffma2(acc[2][4], aB.x, b2p.x); ffma2(acc[3][4], aB.y, b2p.x);
            ffma2(acc[0][5], aA.x, b2p.y); ffma2(acc[1][5], aA.y, b2p.y);
            ffma2(acc[2][5], aB.x, b2p.y); ffma2(acc[3][5], aB.y, b2p.y);
            ffma2(acc[0][6], aA.x, b3p.x); ffma2(acc[1][6], aA.y, b3p.x);
            ffma2(acc[2][6], aB.x, b3p.x); ffma2(acc[3][6], aB.y, b3p.x);
            ffma2(acc[0][7], aA.x, b3p.y); ffma2(acc[1][7], aA.y, b3p.y);
            ffma2(acc[2][7], aB.x, b3p.y); ffma2(acc[3][7], aB.y, b3p.y);
        }
    }

    const float* bp = (n0 & 256) ? bias_b : bias_f;
    float bj[8];
    #pragma unroll
    for (int jj = 0; jj < 4; jj++) {
        bj[jj * 2 + 0] = bp[((n0 & 255) + jj * 32 + tx * 2 + 0) & 255];
        bj[jj * 2 + 1] = bp[((n0 & 255) + jj * 32 + tx * 2 + 1) & 255];
    }
    #pragma unroll
    for (int i = 0; i < 4; i++) {
        const long m = m0 + ty * 8 + i * 2;
        float* r0 = g_xp1 + m * 512;
        float* r1 = r0 + 512;
        #pragma unroll
        for (int jj = 0; jj < 4; jj++) {
            const int n = n0 + jj * 32 + tx * 2;
            const float2 v0 = unpack2(acc[i][jj * 2 + 0]);
            const float2 v1 = unpack2(acc[i][jj * 2 + 1]);
            *(ULL*)(r0 + n) = pack2(v0.x + bj[jj * 2], v1.x + bj[jj * 2 + 1]);
            *(ULL*)(r1 + n) = pack2(v0.y + bj[jj * 2], v1.y + bj[jj * 2 + 1]);
        }
    }
}

// =======================================================================
// Layer-1 biLSTM. grid (64, 2), block 256, 1 CTA/SM, RC=8.
// Merged dot+combine per j; xp prefetched one step ahead; pooled sum in regs.
// =======================================================================
__global__ __launch_bounds__(256, 1) void lstm_l1(
    const float* __restrict__ Whh_f, const float* __restrict__ Whh_b)
{
    const int dir = blockIdx.y;
    const int b0  = blockIdx.x * RC;
    const int tid = threadIdx.x;
    const int u   = tid >> 2;
    const int g   = tid & 3;
    const int row = g * 64 + u;
    const float* Whh = dir ? Whh_b : Whh_f;

    __shared__ __align__(16) float h_s[2][RC * 64];

    ULL w2[32];
    {
        const ULL* wp = (const ULL*)(Whh + row * 64);
        #pragma unroll
        for (int i = 0; i < 32; i++) w2[i] = wp[i];
    }
    const int lane = tid & 31;
    const int qb   = lane & ~3;
    const int col  = dir * 256 + row;

    const float* xpb = g_xp1 + (long)b0 * T * 512 + col;   // + j*T*512 + t*512

    for (int i = tid; i < RC * 64; i += 256) h_s[0][i] = 0.f;

    float c[RC], hsum[RC], xp_cur[RC];
    #pragma unroll
    for (int j = 0; j < RC; j++) { c[j] = 0.f; hsum[j] = 0.f; }
    {
        const int t0 = dir ? (T - 1) : 0;
        #pragma unroll
        for (int j = 0; j < RC; j++)
            xp_cur[j] = __ldg(xpb + (long)j * T * 512 + (long)t0 * 512);
    }
    __syncthreads();

    int p = 0;
    for (int s = 0; s < T; s++) {
        const int sn = (s + 1 < T) ? s + 1 : s;
        const int tn = dir ? (T - 1 - sn) : sn;
        float xp_nxt[RC];
        #pragma unroll
        for (int j = 0; j < RC; j++)
            xp_nxt[j] = __ldg(xpb + (long)j * T * 512 + (long)tn * 512);

        #pragma unroll
        for (int j = 0; j < RC; j++) {
            ULL a0 = 0, a1 = 0;
            const ulonglong2* h4 = (const ulonglong2*)(h_s[p] + j * 64);
            #pragma unroll
            for (int k = 0; k < 16; k++) {
                ulonglong2 hv = h4[k];
                ffma2(a0, w2[2 * k],     hv.x);
                ffma2(a1, w2[2 * k + 1], hv.y);
            }
            const float2 f0 = unpack2(a0), f1 = unpack2(a1);
            float pre = f0.x + f0.y + f1.x + f1.y + xp_cur[j];

            const float act = (g == 2) ? tanh_ap(pre) : sig_ap(pre);
            const float iv = __shfl_sync(0xffffffffu, act, qb + 0);
            const float fv = __shfl_sync(0xffffffffu, act, qb + 1);
            const float gv = __shfl_sync(0xffffffffu, act, qb + 2);
            const float ov = __shfl_sync(0xffffffffu, act, qb + 3);
            c[j] = fmaf(fv, c[j], iv * gv);
            const float h = ov * tanh_ap(c[j]);
            hsum[j] += h;
            if (g == 0) h_s[p ^ 1][j * 64 + u] = h;
        }
        #pragma unroll
        for (int j = 0; j < RC; j++) xp_cur[j] = xp_nxt[j];
        p ^= 1;
        __syncthreads();
    }

    if (g == 0) {
        #pragma unroll
        for (int j = 0; j < RC; j++)
            g_pooled[(b0 + j) * 128 + dir * 64 + u] = hsum[j];
    }
}

// =======================================================================
__global__ void fc_kernel(const float* __restrict__ fcw, const float* __restrict__ fcb,
                          float* __restrict__ out)
{
    const int gw   = (blockIdx.x * blockDim.x + threadIdx.x) >> 5;
    const int lane = threadIdx.x & 31;
    if (gw >= B) return;
    float sum = 0.f;
    #pragma unroll
    for (int qq = 0; qq < 4; qq++)
        sum += g_pooled[gw * 128 + qq * 32 + lane] * fcw[qq * 32 + lane];
    #pragma unroll
    for (int o = 16; o; o >>= 1) sum += __shfl_xor_sync(0xffffffffu, sum, o);
    if (lane == 0) out[gw] = sum * (1.f / 512.f) + fcb[0];
}

// =======================================================================
extern "C" void kernel_launch(void* const* d_in, const int* in_sizes, int n_in,
                              void* d_out, int out_size)
{
    const float* x     = (const float*)d_in[0];
    const float* Wih0f = (const float*)d_in[1];
    const float* Whh0f = (const float*)d_in[2];
    const float* b0f   = (const float*)d_in[3];
    const float* Wih0b = (const float*)d_in[4];
    const float* Whh0b = (const float*)d_in[5];
    const float* b0b   = (const float*)d_in[6];
    const float* Wih1f = (const float*)d_in[7];
    const float* Whh1f = (const float*)d_in[8];
    const float* b1f   = (const float*)d_in[9];
    const float* Wih1b = (const float*)d_in[10];
    const float* Whh1b = (const float*)d_in[11];
    const float* b1b   = (const float*)d_in[12];
    const float* fcw   = (const float*)d_in[13];
    const float* fcb   = (const float*)d_in[14];

    prep_btd<<<128, 512>>>(Wih1f, Wih1b);
    lstm_l0<<<dim3(B / RC, 2), 256>>>(x, Wih0f, Whh0f, b0f, Wih0b, Whh0b, b0b);
    cudaFuncSetAttribute(gemm_xp1, cudaFuncAttributeMaxDynamicSharedMemorySize, SMEM_GEMM);
    gemm_xp1<<<dim3(2048, 4), 256, SMEM_GEMM>>>(b1f, b1b);
    lstm_l1<<<dim3(B / RC, 2), 256>>>(Whh1f, Whh1b);
    fc_kernel<<<32, 512>>>(fcw, fcb, (float*)d_out);
}

// round 7
// speedup vs baseline: 1.5350x; 1.5350x over previous
#include <cuda_runtime.h>
#include <cstdint>

typedef unsigned long long ULL;

// ---------- packed fp32x2 helpers ----------
__device__ __forceinline__ void ffma2(ULL &d, ULL a, ULL b) {
    asm("fma.rn.f32x2 %0, %1, %2, %0;" : "+l"(d) : "l"(a), "l"(b));
}
__device__ __forceinline__ float2 unpack2(ULL v) {
    float2 f; asm("mov.b64 {%0,%1}, %2;" : "=f"(f.x), "=f"(f.y) : "l"(v)); return f;
}
__device__ __forceinline__ ULL pack2(float lo, float hi) {
    ULL r; asm("mov.b64 %0, {%1,%2};" : "=l"(r) : "f"(lo), "f"(hi)); return r;
}

// ---------- activations: single-MUFU tanh ----------
__device__ __forceinline__ float tanh_ap(float x) {
    float r; asm("tanh.approx.f32 %0, %1;" : "=f"(r) : "f"(x)); return r;
}
__device__ __forceinline__ float sig_ap(float x) {
    return fmaf(0.5f, tanh_ap(0.5f * x), 0.5f);
}

// ---------- tf32 rounding (round-to-nearest, keeps fp32 bit layout) ----------
__device__ __forceinline__ float tf32r(float x) {
    uint32_t r; asm("cvt.rna.tf32.f32 %0, %1;" : "=r"(r) : "f"(x));
    return __uint_as_float(r);
}

// ---------- constants ----------
constexpr int B = 512, T = 512;
constexpr long BT = (long)B * T;
constexpr int RC = 4;

// ---------- scratch ----------
__device__ __align__(16) float g_h0T[128 * BT];   // layer-0 out (tf32-rounded), [k][b*T+t]
__device__ __align__(16) float g_xp1[BT * 512];   // layer-1 preacts [b*T+t][n]
__device__ __align__(16) float g_BtT[128 * 512];  // Wih_l1^T (tf32-rounded) [k][n]
__device__ float g_pooled[B * 128];

// =======================================================================
// Layer-0 biLSTM (R5-exact; flush rounds h0 to tf32 for the GEMM).
// grid (128, 2), block 256, 2 CTAs/SM.
// =======================================================================
__global__ __launch_bounds__(256, 2) void lstm_l0(
    const float* __restrict__ x,
    const float* __restrict__ Wih_f, const float* __restrict__ Whh_f, const float* __restrict__ b_f,
    const float* __restrict__ Wih_b, const float* __restrict__ Whh_b, const float* __restrict__ b_b)
{
    const int dir = blockIdx.y;
    const int b0  = blockIdx.x * RC;
    const int tid = threadIdx.x;
    const int u   = tid >> 2;
    const int g   = tid & 3;
    const int row = g * 64 + u;

    const float* Wih = dir ? Wih_b : Wih_f;
    const float* Whh = dir ? Whh_b : Whh_f;
    const float* bb  = dir ? b_b   : b_f;

    __shared__ __align__(16) float h_s[2][RC * 64];
    __shared__ __align__(16) float4 x_s[2][RC];
    __shared__ __align__(16) float hist[RC][64][36];

    ULL w2[32];
    {
        const ULL* wp = (const ULL*)(Whh + row * 64);
        #pragma unroll
        for (int i = 0; i < 32; i++) w2[i] = wp[i];
    }
    const float4 wih = *(const float4*)(Wih + row * 4);
    const float bias = bb[row];

    const int lane = tid & 31;
    const int qb   = lane & ~3;

    for (int i = tid; i < RC * 64; i += 256) h_s[0][i] = 0.f;
    if (tid < RC) {
        const int t0 = dir ? (T - 1) : 0;
        x_s[0][tid] = *(const float4*)(x + ((long)(b0 + tid) * T + t0) * 4);
    }
    __syncthreads();

    float c[RC] = {0.f, 0.f, 0.f, 0.f};
    int p = 0;

    for (int s = 0; s < T; s++) {
        const int t = dir ? (T - 1 - s) : s;
        if (tid < RC) {
            const int sn = (s + 1 < T) ? s + 1 : s;
            const int tn = dir ? (T - 1 - sn) : sn;
            x_s[p ^ 1][tid] = *(const float4*)(x + ((long)(b0 + tid) * T + tn) * 4);
        }

        float pre[RC];
        #pragma unroll
        for (int j = 0; j < RC; j++) {
            ULL a0 = 0, a1 = 0;
            const ulonglong2* h4 = (const ulonglong2*)(h_s[p] + j * 64);
            #pragma unroll
            for (int k = 0; k < 16; k++) {
                ulonglong2 hv = h4[k];
                ffma2(a0, w2[2 * k],     hv.x);
                ffma2(a1, w2[2 * k + 1], hv.y);
            }
            const float2 f0 = unpack2(a0), f1 = unpack2(a1);
            const float4 xv = x_s[p][j];
            pre[j] = f0.x + f0.y + f1.x + f1.y + bias
                   + wih.x * xv.x + wih.y * xv.y + wih.z * xv.z + wih.w * xv.w;
        }

        #pragma unroll
        for (int j = 0; j < RC; j++) {
            const float act = (g == 2) ? tanh_ap(pre[j]) : sig_ap(pre[j]);
            const float iv = __shfl_sync(0xffffffffu, act, qb + 0);
            const float fv = __shfl_sync(0xffffffffu, act, qb + 1);
            const float gv = __shfl_sync(0xffffffffu, act, qb + 2);
            const float ov = __shfl_sync(0xffffffffu, act, qb + 3);
            c[j] = fmaf(fv, c[j], iv * gv);
            const float h = ov * tanh_ap(c[j]);
            if (g == 0) {
                h_s[p ^ 1][j * 64 + u] = h;
                hist[j][u][t & 31] = h;
            }
        }
        p ^= 1;
        __syncthreads();

        if ((s & 31) == 31) {
            const int tbase = t & ~31;
            #pragma unroll
            for (int w = 0; w < 8; w++) {
                const int e   = tid + w * 256;
                const int tw4 = e & 7;
                const int ju  = e >> 3;
                const int j   = ju >> 6, uu = ju & 63;
                float4 v = *(const float4*)(&hist[j][uu][tw4 * 4]);
                v.x = tf32r(v.x); v.y = tf32r(v.y); v.z = tf32r(v.z); v.w = tf32r(v.w);
                *(float4*)(g_h0T + (long)(dir * 64 + uu) * BT + (long)(b0 + j) * T + tbase + tw4 * 4) = v;
            }
            __syncthreads();
        }
    }
}

// =======================================================================
// Prep: g_BtT[k][n] = tf32(Wih_l1[n][k])   (n = dir*256 + gate_row)
// =======================================================================
__global__ void prep_btT(const float* __restrict__ Wf, const float* __restrict__ Wb)
{
    const int idx = blockIdx.x * 512 + threadIdx.x;   // 65536
    const int k = idx >> 9, n = idx & 511;
    const float* W = (n & 256) ? Wb : Wf;
    g_BtT[idx] = tf32r(W[(n & 255) * 128 + k]);
}

// =======================================================================
// xp1 GEMM via tf32 tensor cores (mma.sync.m16n8k8).
// CTA tile 128m x 128n, K split 2x64. 8 warps: warp_m = wid&3 (32m),
// warp_n = wid>>2 (64n). Per warp per k8: 2 A-frags + 8 B-frags, 16 mma.
// Smem [k][.] with 136-float row pad -> 8c+r bank map, conflict-free.
// grid (2048, 4), block 256, 2 CTAs/SM.
// =======================================================================
constexpr int FP = 136;
constexpr int SMEM_GEMM = 2 * 64 * FP * 4;   // 69632 B

__global__ __launch_bounds__(256, 2) void gemm_xp1(
    const float* __restrict__ bias_f, const float* __restrict__ bias_b)
{
    extern __shared__ char smraw[];
    float* As = (float*)smraw;                   // [64][FP]  m fastest
    float* Bs = (float*)(smraw + 64 * FP * 4);   // [64][FP]  n fastest
    const int tid  = threadIdx.x;
    const int lane = tid & 31;
    const int wid  = tid >> 5;
    const int g    = lane >> 2;       // group id (row within fragment)
    const int cc   = lane & 3;        // k-offset within fragment
    const int wm   = (wid & 3) * 32;  // warp m-base
    const int wn   = (wid >> 2) * 64; // warp n-base
    const long m0 = (long)blockIdx.x * 128;
    const int  n0 = blockIdx.y * 128;

    float acc[2][8][4];
    #pragma unroll
    for (int i = 0; i < 2; i++)
        #pragma unroll
        for (int j = 0; j < 8; j++)
            #pragma unroll
            for (int q = 0; q < 4; q++) acc[i][j][q] = 0.f;

    for (int kc = 0; kc < 2; kc++) {
        const int k0 = kc * 64;
        __syncthreads();
        #pragma unroll
        for (int i = 0; i < 8; i++) {
            const int e = tid + i * 256;
            const int k = e >> 5, m4 = (e & 31) * 4;
            *(float4*)(As + k * FP + m4) = *(const float4*)(g_h0T + (long)(k0 + k) * BT + m0 + m4);
        }
        #pragma unroll
        for (int i = 0; i < 8; i++) {
            const int e = tid + i * 256;
            const int k = e >> 5, n4 = (e & 31) * 4;
            *(float4*)(Bs + k * FP + n4) = *(const float4*)(g_BtT + (long)(k0 + k) * 512 + n0 + n4);
        }
        __syncthreads();

        #pragma unroll
        for (int kk = 0; kk < 8; kk++) {
            const float* abase = As + (kk * 8 + cc) * FP + wm + g;
            uint32_t a0[2], a1[2], a2[2], a3[2];
            #pragma unroll
            for (int i = 0; i < 2; i++) {
                const float* ap = abase + 16 * i;
                a0[i] = __float_as_uint(ap[0]);
                a1[i] = __float_as_uint(ap[8]);
                a2[i] = __float_as_uint(ap[4 * FP]);
                a3[i] = __float_as_uint(ap[4 * FP + 8]);
            }
            const float* bbase = Bs + (kk * 8 + cc) * FP + wn + g;
            uint32_t b0[8], b1[8];
            #pragma unroll
            for (int j = 0; j < 8; j++) {
                b0[j] = __float_as_uint(bbase[8 * j]);
                b1[j] = __float_as_uint(bbase[8 * j + 4 * FP]);
            }
            #pragma unroll
            for (int i = 0; i < 2; i++)
                #pragma unroll
                for (int j = 0; j < 8; j++) {
                    asm("mma.sync.aligned.m16n8k8.row.col.f32.tf32.tf32.f32 "
                        "{%0,%1,%2,%3}, {%4,%5,%6,%7}, {%8,%9}, {%0,%1,%2,%3};"
                        : "+f"(acc[i][j][0]), "+f"(acc[i][j][1]),
                          "+f"(acc[i][j][2]), "+f"(acc[i][j][3])
                        : "r"(a0[i]), "r"(a1[i]), "r"(a2[i]), "r"(a3[i]),
                          "r"(b0[j]), "r"(b1[j]));
                }
        }
    }

    // epilogue: + bias, ULL stores (2 consecutive n per thread)
    const float* bp = (n0 & 256) ? bias_b : bias_f;
    float bn0[8], bn1[8];
    #pragma unroll
    for (int j = 0; j < 8; j++) {
        const int n = ((n0 & 255) + wn + 8 * j + cc * 2);
        bn0[j] = bp[n & 255];
        bn1[j] = bp[(n + 1) & 255];
    }
    #pragma unroll
    for (int i = 0; i < 2; i++) {
        const long mrow = m0 + wm + 16 * i + g;
        float* r0 = g_xp1 + mrow * 512;
        float* r1 = r0 + 8 * 512;
        #pragma unroll
        for (int j = 0; j < 8; j++) {
            const int n = n0 + wn + 8 * j + cc * 2;
            *(ULL*)(r0 + n) = pack2(acc[i][j][0] + bn0[j], acc[i][j][1] + bn1[j]);
            *(ULL*)(r1 + n) = pack2(acc[i][j][2] + bn0[j], acc[i][j][3] + bn1[j]);
        }
    }
}

// =======================================================================
// Layer-1 biLSTM (R5-exact). grid (128, 2), block 256, 2 CTAs/SM.
// =======================================================================
__global__ __launch_bounds__(256, 2) void lstm_l1(
    const float* __restrict__ Whh_f, const float* __restrict__ Whh_b)
{
    const int dir = blockIdx.y;
    const int b0  = blockIdx.x * RC;
    const int tid = threadIdx.x;
    const int u   = tid >> 2;
    const int g   = tid & 3;
    const int row = g * 64 + u;
    const float* Whh = dir ? Whh_b : Whh_f;

    __shared__ __align__(16) float h_s[2][RC * 64];

    ULL w2[32];
    {
        const ULL* wp = (const ULL*)(Whh + row * 64);
        #pragma unroll
        for (int i = 0; i < 32; i++) w2[i] = wp[i];
    }
    const int lane = tid & 31;
    const int qb   = lane & ~3;
    const int col  = dir * 256 + row;

    const float* xp_base[RC];
    #pragma unroll
    for (int j = 0; j < RC; j++)
        xp_base[j] = g_xp1 + (long)(b0 + j) * T * 512 + col;

    for (int i = tid; i < RC * 64; i += 256) h_s[0][i] = 0.f;

    float c[RC]    = {0.f, 0.f, 0.f, 0.f};
    float hsum[RC] = {0.f, 0.f, 0.f, 0.f};
    float xp_cur[RC];
    {
        const int t0 = dir ? (T - 1) : 0;
        #pragma unroll
        for (int j = 0; j < RC; j++) xp_cur[j] = __ldg(xp_base[j] + (long)t0 * 512);
    }
    __syncthreads();

    int p = 0;
    for (int s = 0; s < T; s++) {
        const int sn = (s + 1 < T) ? s + 1 : s;
        const int tn = dir ? (T - 1 - sn) : sn;
        float xp_nxt[RC];
        #pragma unroll
        for (int j = 0; j < RC; j++) xp_nxt[j] = __ldg(xp_base[j] + (long)tn * 512);

        float pre[RC];
        #pragma unroll
        for (int j = 0; j < RC; j++) {
            ULL a0 = 0, a1 = 0;
            const ulonglong2* h4 = (const ulonglong2*)(h_s[p] + j * 64);
            #pragma unroll
            for (int k = 0; k < 16; k++) {
                ulonglong2 hv = h4[k];
                ffma2(a0, w2[2 * k],     hv.x);
                ffma2(a1, w2[2 * k + 1], hv.y);
            }
            const float2 f0 = unpack2(a0), f1 = unpack2(a1);
            pre[j] = f0.x + f0.y + f1.x + f1.y + xp_cur[j];
        }

        #pragma unroll
        for (int j = 0; j < RC; j++) {
            const float act = (g == 2) ? tanh_ap(pre[j]) : sig_ap(pre[j]);
            const float iv = __shfl_sync(0xffffffffu, act, qb + 0);
            const float fv = __shfl_sync(0xffffffffu, act, qb + 1);
            const float gv = __shfl_sync(0xffffffffu, act, qb + 2);
            const float ov = __shfl_sync(0xffffffffu, act, qb + 3);
            c[j] = fmaf(fv, c[j], iv * gv);
            const float h = ov * tanh_ap(c[j]);
            hsum[j] += h;
            if (g == 0) h_s[p ^ 1][j * 64 + u] = h;
        }
        #pragma unroll
        for (int j = 0; j < RC; j++) xp_cur[j] = xp_nxt[j];
        p ^= 1;
        __syncthreads();
    }

    if (g == 0) {
        #pragma unroll
        for (int j = 0; j < RC; j++)
            g_pooled[(b0 + j) * 128 + dir * 64 + u] = hsum[j];
    }
}

// =======================================================================
__global__ void fc_kernel(const float* __restrict__ fcw, const float* __restrict__ fcb,
                          float* __restrict__ out)
{
    const int gw   = (blockIdx.x * blockDim.x + threadIdx.x) >> 5;
    const int lane = threadIdx.x & 31;
    if (gw >= B) return;
    float sum = 0.f;
    #pragma unroll
    for (int qq = 0; qq < 4; qq++)
        sum += g_pooled[gw * 128 + qq * 32 + lane] * fcw[qq * 32 + lane];
    #pragma unroll
    for (int o = 16; o; o >>= 1) sum += __shfl_xor_sync(0xffffffffu, sum, o);
    if (lane == 0) out[gw] = sum * (1.f / 512.f) + fcb[0];
}

// =======================================================================
extern "C" void kernel_launch(void* const* d_in, const int* in_sizes, int n_in,
                              void* d_out, int out_size)
{
    const float* x     = (const float*)d_in[0];
    const float* Wih0f = (const float*)d_in[1];
    const float* Whh0f = (const float*)d_in[2];
    const float* b0f   = (const float*)d_in[3];
    const float* Wih0b = (const float*)d_in[4];
    const float* Whh0b = (const float*)d_in[5];
    const float* b0b   = (const float*)d_in[6];
    const float* Wih1f = (const float*)d_in[7];
    const float* Whh1f = (const float*)d_in[8];
    const float* b1f   = (const float*)d_in[9];
    const float* Wih1b = (const float*)d_in[10];
    const float* Whh1b = (const float*)d_in[11];
    const float* b1b   = (const float*)d_in[12];
    const float* fcw   = (const float*)d_in[13];
    const float* fcb   = (const float*)d_in[14];

    prep_btT<<<128, 512>>>(Wih1f, Wih1b);
    lstm_l0<<<dim3(B / RC, 2), 256>>>(x, Wih0f, Whh0f, b0f, Wih0b, Whh0b, b0b);
    cudaFuncSetAttribute(gemm_xp1, cudaFuncAttributeMaxDynamicSharedMemorySize, SMEM_GEMM);
    gemm_xp1<<<dim3(2048, 4), 256, SMEM_GEMM>>>(b1f, b1b);
    lstm_l1<<<dim3(B / RC, 2), 256>>>(Whh1f, Whh1b);
    fc_kernel<<<32, 512>>>(fcw, fcb, (float*)d_out);
}

// round 8
// speedup vs baseline: 1.7086x; 1.1130x over previous
#include <cuda_runtime.h>
#include <cstdint>

typedef unsigned long long ULL;

// ---------- packed fp32x2 helpers ----------
__device__ __forceinline__ void ffma2(ULL &d, ULL a, ULL b) {
    asm("fma.rn.f32x2 %0, %1, %2, %0;" : "+l"(d) : "l"(a), "l"(b));
}
__device__ __forceinline__ float2 unpack2(ULL v) {
    float2 f; asm("mov.b64 {%0,%1}, %2;" : "=f"(f.x), "=f"(f.y) : "l"(v)); return f;
}
__device__ __forceinline__ ULL pack2(float lo, float hi) {
    ULL r; asm("mov.b64 %0, {%1,%2};" : "=l"(r) : "f"(lo), "f"(hi)); return r;
}

// ---------- activations: single-MUFU tanh ----------
__device__ __forceinline__ float tanh_ap(float x) {
    float r; asm("tanh.approx.f32 %0, %1;" : "=f"(r) : "f"(x)); return r;
}
__device__ __forceinline__ float sig_ap(float x) {
    return fmaf(0.5f, tanh_ap(0.5f * x), 0.5f);
}

// ---------- tf32 rounding ----------
__device__ __forceinline__ float tf32r(float x) {
    uint32_t r; asm("cvt.rna.tf32.f32 %0, %1;" : "=r"(r) : "f"(x));
    return __uint_as_float(r);
}

// ---------- cp.async 16B ----------
__device__ __forceinline__ void cp16(uint32_t dst_smem, const void* src) {
    asm volatile("cp.async.cg.shared.global [%0], [%1], 16;" :: "r"(dst_smem), "l"(src) : "memory");
}
__device__ __forceinline__ void cp_commit() { asm volatile("cp.async.commit_group;"); }
__device__ __forceinline__ void cp_wait0()  { asm volatile("cp.async.wait_group 0;" ::: "memory"); }

// ---------- constants ----------
constexpr int B = 512, T = 512;
constexpr long BT = (long)B * T;
constexpr int RC = 4;

// ---------- scratch ----------
__device__ __align__(16) float g_h0T[128 * BT];   // layer-0 out (tf32-rounded), [k][b*T+t]
__device__ __align__(16) float g_xp1[BT * 512];   // layer-1 preacts [b*T+t][n]
__device__ __align__(16) float g_BtT[128 * 512];  // Wih_l1^T (tf32-rounded) [k][n]
__device__ float g_pooled[B * 128];

// =======================================================================
// Layer-0 biLSTM (R5/R7-exact). grid (128, 2), block 256, 2 CTAs/SM.
// =======================================================================
__global__ __launch_bounds__(256, 2) void lstm_l0(
    const float* __restrict__ x,
    const float* __restrict__ Wih_f, const float* __restrict__ Whh_f, const float* __restrict__ b_f,
    const float* __restrict__ Wih_b, const float* __restrict__ Whh_b, const float* __restrict__ b_b)
{
    const int dir = blockIdx.y;
    const int b0  = blockIdx.x * RC;
    const int tid = threadIdx.x;
    const int u   = tid >> 2;
    const int g   = tid & 3;
    const int row = g * 64 + u;

    const float* Wih = dir ? Wih_b : Wih_f;
    const float* Whh = dir ? Whh_b : Whh_f;
    const float* bb  = dir ? b_b   : b_f;

    __shared__ __align__(16) float h_s[2][RC * 64];
    __shared__ __align__(16) float4 x_s[2][RC];
    __shared__ __align__(16) float hist[RC][64][36];

    ULL w2[32];
    {
        const ULL* wp = (const ULL*)(Whh + row * 64);
        #pragma unroll
        for (int i = 0; i < 32; i++) w2[i] = wp[i];
    }
    const float4 wih = *(const float4*)(Wih + row * 4);
    const float bias = bb[row];

    const int lane = tid & 31;
    const int qb   = lane & ~3;

    for (int i = tid; i < RC * 64; i += 256) h_s[0][i] = 0.f;
    if (tid < RC) {
        const int t0 = dir ? (T - 1) : 0;
        x_s[0][tid] = *(const float4*)(x + ((long)(b0 + tid) * T + t0) * 4);
    }
    __syncthreads();

    float c[RC] = {0.f, 0.f, 0.f, 0.f};
    int p = 0;

    for (int s = 0; s < T; s++) {
        const int t = dir ? (T - 1 - s) : s;
        if (tid < RC) {
            const int sn = (s + 1 < T) ? s + 1 : s;
            const int tn = dir ? (T - 1 - sn) : sn;
            x_s[p ^ 1][tid] = *(const float4*)(x + ((long)(b0 + tid) * T + tn) * 4);
        }

        float pre[RC];
        #pragma unroll
        for (int j = 0; j < RC; j++) {
            ULL a0 = 0, a1 = 0;
            const ulonglong2* h4 = (const ulonglong2*)(h_s[p] + j * 64);
            #pragma unroll
            for (int k = 0; k < 16; k++) {
                ulonglong2 hv = h4[k];
                ffma2(a0, w2[2 * k],     hv.x);
                ffma2(a1, w2[2 * k + 1], hv.y);
            }
            const float2 f0 = unpack2(a0), f1 = unpack2(a1);
            const float4 xv = x_s[p][j];
            pre[j] = f0.x + f0.y + f1.x + f1.y + bias
                   + wih.x * xv.x + wih.y * xv.y + wih.z * xv.z + wih.w * xv.w;
        }

        #pragma unroll
        for (int j = 0; j < RC; j++) {
            const float act = (g == 2) ? tanh_ap(pre[j]) : sig_ap(pre[j]);
            const float iv = __shfl_sync(0xffffffffu, act, qb + 0);
            const float fv = __shfl_sync(0xffffffffu, act, qb + 1);
            const float gv = __shfl_sync(0xffffffffu, act, qb + 2);
            const float ov = __shfl_sync(0xffffffffu, act, qb + 3);
            c[j] = fmaf(fv, c[j], iv * gv);
            const float h = ov * tanh_ap(c[j]);
            if (g == 0) {
                h_s[p ^ 1][j * 64 + u] = h;
                hist[j][u][t & 31] = h;
            }
        }
        p ^= 1;
        __syncthreads();

        if ((s & 31) == 31) {
            const int tbase = t & ~31;
            #pragma unroll
            for (int w = 0; w < 8; w++) {
                const int e   = tid + w * 256;
                const int tw4 = e & 7;
                const int ju  = e >> 3;
                const int j   = ju >> 6, uu = ju & 63;
                float4 v = *(const float4*)(&hist[j][uu][tw4 * 4]);
                v.x = tf32r(v.x); v.y = tf32r(v.y); v.z = tf32r(v.z); v.w = tf32r(v.w);
                *(float4*)(g_h0T + (long)(dir * 64 + uu) * BT + (long)(b0 + j) * T + tbase + tw4 * 4) = v;
            }
            __syncthreads();
        }
    }
}

// =======================================================================
// Prep: g_BtT[k][n] = tf32(Wih_l1[n][k])   (n = dir*256 + gate_row)
// =======================================================================
__global__ void prep_btT(const float* __restrict__ Wf, const float* __restrict__ Wb)
{
    const int idx = blockIdx.x * 512 + threadIdx.x;   // 65536
    const int k = idx >> 9, n = idx & 511;
    const float* W = (n & 256) ? Wb : Wf;
    g_BtT[idx] = tf32r(W[(n & 255) * 128 + k]);
}

// =======================================================================
// xp1 GEMM via tf32 mma.sync.m16n8k8, double-buffered cp.async pipeline.
// CTA tile 128m x 128n, K = 4 slabs of 32. grid (2048, 4), blk 256, 2 CTAs/SM.
// =======================================================================
constexpr int FP = 136;
constexpr int KS = 32;
constexpr int SLAB = KS * FP;                 // floats per A (or B) slab
constexpr int SMEM_GEMM = 2 * 2 * SLAB * 4;   // 69632 B

__global__ __launch_bounds__(256, 2) void gemm_xp1(
    const float* __restrict__ bias_f, const float* __restrict__ bias_b)
{
    extern __shared__ float sm[];   // [buf][{A,B}][KS][FP]
    const uint32_t smB = (uint32_t)__cvta_generic_to_shared(sm);
    const int tid  = threadIdx.x;
    const int lane = tid & 31;
    const int wid  = tid >> 5;
    const int g    = lane >> 2;
    const int cc   = lane & 3;
    const int wm   = (wid & 3) * 32;
    const int wn   = (wid >> 2) * 64;
    const long m0 = (long)blockIdx.x * 128;
    const int  n0 = blockIdx.y * 128;

    float acc[2][8][4];
    #pragma unroll
    for (int i = 0; i < 2; i++)
        #pragma unroll
        for (int j = 0; j < 8; j++)
            #pragma unroll
            for (int q = 0; q < 4; q++) acc[i][j][q] = 0.f;

    const int lk = tid >> 5;          // 0..7: k-row block base (each loads 4 rows)
    const int lm4 = (tid & 31) * 4;   // col within row

    // slab loader: A rows from g_h0T, B rows from g_BtT
    auto load_slab = [&](int buf, int kc) {
        const long kg = (long)kc * KS;
        const uint32_t abase = smB + (uint32_t)(buf * 2 * SLAB) * 4;
        const uint32_t bbase = abase + (uint32_t)SLAB * 4;
        #pragma unroll
        for (int i = 0; i < 4; i++) {
            const int k = lk + i * 8;
            cp16(abase + (uint32_t)(k * FP + lm4) * 4, g_h0T + (kg + k) * BT + m0 + lm4);
        }
        #pragma unroll
        for (int i = 0; i < 4; i++) {
            const int k = lk + i * 8;
            cp16(bbase + (uint32_t)(k * FP + lm4) * 4, g_BtT + (kg + k) * 512 + n0 + lm4);
        }
    };

    load_slab(0, 0);
    cp_commit();

    int buf = 0;
    for (int kc = 0; kc < 4; kc++) {
        cp_wait0();
        __syncthreads();            // slab `buf` ready; buf^1 free (all warps past kc-1)
        if (kc < 3) { load_slab(buf ^ 1, kc + 1); cp_commit(); }

        const float* As = sm + buf * 2 * SLAB;
        const float* Bs = As + SLAB;
        #pragma unroll
        for (int kk = 0; kk < KS / 8; kk++) {
            const float* abase = As + (kk * 8 + cc) * FP + wm + g;
            uint32_t a0[2], a1[2], a2[2], a3[2];
            #pragma unroll
            for (int i = 0; i < 2; i++) {
                const float* ap = abase + 16 * i;
                a0[i] = __float_as_uint(ap[0]);
                a1[i] = __float_as_uint(ap[8]);
                a2[i] = __float_as_uint(ap[4 * FP]);
                a3[i] = __float_as_uint(ap[4 * FP + 8]);
            }
            const float* bbase = Bs + (kk * 8 + cc) * FP + wn + g;
            uint32_t b0[8], b1[8];
            #pragma unroll
            for (int j = 0; j < 8; j++) {
                b0[j] = __float_as_uint(bbase[8 * j]);
                b1[j] = __float_as_uint(bbase[8 * j + 4 * FP]);
            }
            #pragma unroll
            for (int i = 0; i < 2; i++)
                #pragma unroll
                for (int j = 0; j < 8; j++) {
                    asm("mma.sync.aligned.m16n8k8.row.col.f32.tf32.tf32.f32 "
                        "{%0,%1,%2,%3}, {%4,%5,%6,%7}, {%8,%9}, {%0,%1,%2,%3};"
                        : "+f"(acc[i][j][0]), "+f"(acc[i][j][1]),
                          "+f"(acc[i][j][2]), "+f"(acc[i][j][3])
                        : "r"(a0[i]), "r"(a1[i]), "r"(a2[i]), "r"(a3[i]),
                          "r"(b0[j]), "r"(b1[j]));
                }
        }
        buf ^= 1;
        __syncthreads();            // all warps done reading before this slab is reloaded
    }

    // epilogue: + bias, ULL stores
    const float* bp = (n0 & 256) ? bias_b : bias_f;
    float bn0[8], bn1[8];
    #pragma unroll
    for (int j = 0; j < 8; j++) {
        const int n = ((n0 & 255) + wn + 8 * j + cc * 2);
        bn0[j] = bp[n & 255];
        bn1[j] = bp[(n + 1) & 255];
    }
    #pragma unroll
    for (int i = 0; i < 2; i++) {
        const long mrow = m0 + wm + 16 * i + g;
        float* r0 = g_xp1 + mrow * 512;
        float* r1 = r0 + 8 * 512;
        #pragma unroll
        for (int j = 0; j < 8; j++) {
            const int n = n0 + wn + 8 * j + cc * 2;
            *(ULL*)(r0 + n) = pack2(acc[i][j][0] + bn0[j], acc[i][j][1] + bn1[j]);
            *(ULL*)(r1 + n) = pack2(acc[i][j][2] + bn0[j], acc[i][j][3] + bn1[j]);
        }
    }
}

// =======================================================================
// Layer-1 biLSTM (R5 core; xp stream staged via coalesced cp.async).
// grid (128, 2), block 256, 2 CTAs/SM.
// xp_s layout [buf][j][g][72]: 8g+u bank map -> conflict-free LDS.
// =======================================================================
__global__ __launch_bounds__(256, 2) void lstm_l1(
    const float* __restrict__ Whh_f, const float* __restrict__ Whh_b)
{
    const int dir = blockIdx.y;
    const int b0  = blockIdx.x * RC;
    const int tid = threadIdx.x;
    const int u   = tid >> 2;
    const int g   = tid & 3;
    const int row = g * 64 + u;
    const float* Whh = dir ? Whh_b : Whh_f;

    __shared__ __align__(16) float h_s[2][RC * 64];
    __shared__ __align__(16) float xp_s[2][RC][4][72];

    ULL w2[32];
    {
        const ULL* wp = (const ULL*)(Whh + row * 64);
        #pragma unroll
        for (int i = 0; i < 32; i++) w2[i] = wp[i];
    }
    const int lane = tid & 31;
    const int qb   = lane & ~3;

    // staging role: thread -> (j_st, g_st, u4_st) covering xp[j][dir*256 + c*4 ..+3]
    const int j_st  = tid >> 6;
    const int c_st  = tid & 63;
    const int g_st  = c_st >> 4;
    const int u4_st = (c_st & 15) * 4;
    const uint32_t xpsB = (uint32_t)__cvta_generic_to_shared(&xp_s[0][0][0][0]);
    const uint32_t st_off = (uint32_t)(((j_st * 4 + g_st) * 72 + u4_st) * 4);
    const uint32_t buf_stride = (uint32_t)(RC * 4 * 72 * 4);
    const float* xp_src = g_xp1 + (long)(b0 + j_st) * T * 512 + dir * 256 + c_st * 4;

    for (int i = tid; i < RC * 64; i += 256) h_s[0][i] = 0.f;

    float c[RC]    = {0.f, 0.f, 0.f, 0.f};
    float hsum[RC] = {0.f, 0.f, 0.f, 0.f};
    {
        const int t0 = dir ? (T - 1) : 0;
        cp16(xpsB + st_off, xp_src + (long)t0 * 512);
        cp_commit();
        cp_wait0();
    }
    __syncthreads();

    int p = 0;
    for (int s = 0; s < T; s++) {
        if (s + 1 < T) {
            const int tn = dir ? (T - 2 - s) : (s + 1);
            cp16(xpsB + (p ^ 1) * buf_stride + st_off, xp_src + (long)tn * 512);
            cp_commit();
        }

        float pre[RC];
        #pragma unroll
        for (int j = 0; j < RC; j++) {
            ULL a0 = 0, a1 = 0;
            const ulonglong2* h4 = (const ulonglong2*)(h_s[p] + j * 64);
            #pragma unroll
            for (int k = 0; k < 16; k++) {
                ulonglong2 hv = h4[k];
                ffma2(a0, w2[2 * k],     hv.x);
                ffma2(a1, w2[2 * k + 1], hv.y);
            }
            const float2 f0 = unpack2(a0), f1 = unpack2(a1);
            pre[j] = f0.x + f0.y + f1.x + f1.y + xp_s[p][j][g][u];
        }

        #pragma unroll
        for (int j = 0; j < RC; j++) {
            const float act = (g == 2) ? tanh_ap(pre[j]) : sig_ap(pre[j]);
            const float iv = __shfl_sync(0xffffffffu, act, qb + 0);
            const float fv = __shfl_sync(0xffffffffu, act, qb + 1);
            const float gv = __shfl_sync(0xffffffffu, act, qb + 2);
            const float ov = __shfl_sync(0xffffffffu, act, qb + 3);
            c[j] = fmaf(fv, c[j], iv * gv);
            const float h = ov * tanh_ap(c[j]);
            hsum[j] += h;
            if (g == 0) h_s[p ^ 1][j * 64 + u] = h;
        }
        cp_wait0();
        p ^= 1;
        __syncthreads();
    }

    if (g == 0) {
        #pragma unroll
        for (int j = 0; j < RC; j++)
            g_pooled[(b0 + j) * 128 + dir * 64 + u] = hsum[j];
    }
}

// =======================================================================
__global__ void fc_kernel(const float* __restrict__ fcw, const float* __restrict__ fcb,
                          float* __restrict__ out)
{
    const int gw   = (blockIdx.x * blockDim.x + threadIdx.x) >> 5;
    const int lane = threadIdx.x & 31;
    if (gw >= B) return;
    float sum = 0.f;
    #pragma unroll
    for (int qq = 0; qq < 4; qq++)
        sum += g_pooled[gw * 128 + qq * 32 + lane] * fcw[qq * 32 + lane];
    #pragma unroll
    for (int o = 16; o; o >>= 1) sum += __shfl_xor_sync(0xffffffffu, sum, o);
    if (lane == 0) out[gw] = sum * (1.f / 512.f) + fcb[0];
}

// =======================================================================
extern "C" void kernel_launch(void* const* d_in, const int* in_sizes, int n_in,
                              void* d_out, int out_size)
{
    const float* x     = (const float*)d_in[0];
    const float* Wih0f = (const float*)d_in[1];
    const float* Whh0f = (const float*)d_in[2];
    const float* b0f   = (const float*)d_in[3];
    const float* Wih0b = (const float*)d_in[4];
    const float* Whh0b = (const float*)d_in[5];
    const float* b0b   = (const float*)d_in[6];
    const float* Wih1f = (const float*)d_in[7];
    const float* Whh1f = (const float*)d_in[8];
    const float* b1f   = (const float*)d_in[9];
    const float* Wih1b = (const float*)d_in[10];
    const float* Whh1b = (const float*)d_in[11];
    const float* b1b   = (const float*)d_in[12];
    const float* fcw   = (const float*)d_in[13];
    const float* fcb   = (const float*)d_in[14];

    prep_btT<<<128, 512>>>(Wih1f, Wih1b);
    lstm_l0<<<dim3(B / RC, 2), 256>>>(x, Wih0f, Whh0f, b0f, Wih0b, Whh0b, b0b);
    cudaFuncSetAttribute(gemm_xp1, cudaFuncAttributeMaxDynamicSharedMemorySize, SMEM_GEMM);
    gemm_xp1<<<dim3(2048, 4), 256, SMEM_GEMM>>>(b1f, b1b);
    lstm_l1<<<dim3(B / RC, 2), 256>>>(Whh1f, Whh1b);
    fc_kernel<<<32, 512>>>(fcw, fcb, (float*)d_out);
}